// round 5
// baseline (speedup 1.0000x reference)
#include <cuda_runtime.h>
#include <math.h>

#define BB 64
#define SS 64
#define EE 256
#define HH 512
#define VV 30000
#define TT 32
#define GG 1536
#define NBF 118          // ceil(30000/256)
#define ENB 96           // encoder persistent blocks
#define SMEM_ENC ((16*516 + 64*68)*4)

__device__ float g_ex[BB*SS*EE];
__device__ float g_gi[BB*SS*GG];
__device__ float g_enc[BB*SS*HH];
__device__ float g_temp[BB*SS*HH];
__device__ float g_h[BB*HH];
__device__ float g_gh[BB*GG];
__device__ float g_v[BB*1280];           // [emb|ctx|h]
__device__ float g_u[BB*1024];           // [h|ctx]
__device__ float g_pa[4*BB*GG];
__device__ float g_pb[4*BB*GG];
__device__ float g_pmax[BB*128];
__device__ int   g_pidx[BB*128];
__device__ unsigned g_cnt = 0, g_gen = 0;

__device__ __forceinline__ float sigmoidf_(float x){ return 1.0f/(1.0f+expf(-x)); }

__device__ __forceinline__ void gridbar(){
    __threadfence();
    __syncthreads();
    if (threadIdx.x == 0){
        unsigned gen = *(volatile unsigned*)&g_gen;
        if (atomicAdd(&g_cnt, 1u) == ENB-1u){
            g_cnt = 0;
            __threadfence();
            atomicAdd(&g_gen, 1u);
        } else {
            while (*(volatile unsigned*)&g_gen == gen) __nanosleep(32);
        }
    }
    __syncthreads();
}

__global__ __launch_bounds__(64) void k_embed(const int* __restrict__ x,
                                              const float* __restrict__ emb){
    int i = blockIdx.x;
    int tok = x[i];
    const float4* s = (const float4*)(emb + (size_t)tok*EE);
    ((float4*)(g_ex + (size_t)i*EE))[threadIdx.x] = s[threadIdx.x];
}

// C[M,N] = A @ W^T + bias. which==0: g_ex->g_gi ; which==1: g_enc->g_temp
__global__ __launch_bounds__(256) void k_sgemm(int which,
    const float* __restrict__ W, int ldw, const float* __restrict__ bias, int K)
{
    const float* A; float* C; int lda, ldc;
    if (which == 0) { A = g_ex;  lda = EE; C = g_gi;   ldc = GG; }
    else            { A = g_enc; lda = HH; C = g_temp; ldc = HH; }
    __shared__ float As[16][64];
    __shared__ float Ws[16][64];
    int tid = threadIdx.x;
    int tx = tid & 15, ty = tid >> 4;
    int n0 = blockIdx.x * 64, m0 = blockIdx.y * 64;
    int lr = tid >> 2, lk = (tid & 3) << 2;
    float acc[4][4] = {};
    const float* Ap = A + (size_t)(m0 + lr)*lda + lk;
    const float* Wp = W + (size_t)(n0 + lr)*ldw + lk;
    for (int k0 = 0; k0 < K; k0 += 16) {
        float4 a4 = *(const float4*)(Ap + k0);
        float4 w4 = *(const float4*)(Wp + k0);
        As[lk+0][lr]=a4.x; As[lk+1][lr]=a4.y; As[lk+2][lr]=a4.z; As[lk+3][lr]=a4.w;
        Ws[lk+0][lr]=w4.x; Ws[lk+1][lr]=w4.y; Ws[lk+2][lr]=w4.z; Ws[lk+3][lr]=w4.w;
        __syncthreads();
        #pragma unroll
        for (int k = 0; k < 16; k++) {
            float4 a = *(const float4*)&As[k][ty<<2];
            float4 b = *(const float4*)&Ws[k][tx<<2];
            float av[4]={a.x,a.y,a.z,a.w}, bv[4]={b.x,b.y,b.z,b.w};
            #pragma unroll
            for (int i=0;i<4;i++)
                #pragma unroll
                for (int j=0;j<4;j++) acc[i][j] += av[i]*bv[j];
        }
        __syncthreads();
    }
    #pragma unroll
    for (int i=0;i<4;i++){
        int m = m0 + (ty<<2) + i;
        #pragma unroll
        for (int j=0;j<4;j++){
            int n = n0 + (tx<<2) + j;
            C[(size_t)m*ldc + n] = acc[i][j] + bias[n];
        }
    }
}

// persistent fused encoder: 64 GRU steps, one launch
__global__ __launch_bounds__(256) void k_encoder(const float* __restrict__ Whh,
                                                 const float* __restrict__ bhh){
    extern __shared__ float sm[];
    float* Wsl = sm;              // [16][516]
    float* hs  = sm + 16*516;     // [64][68]
    int tid = threadIdx.x, bid = blockIdx.x;
    int n0 = bid*16;
    for (int f = tid; f < 16*128; f += 256){
        int r = f >> 7, c = (f & 127) << 2;
        float4 w = *(const float4*)(Whh + (size_t)(n0+r)*HH + c);
        float* d = Wsl + r*516 + c;
        d[0]=w.x; d[1]=w.y; d[2]=w.z; d[3]=w.w;
    }
    int nl = tid & 15, bg = tid >> 4;
    for (int t = 0; t < SS; t++){
        if (t > 0){
            float a0=0.f,a1=0.f,a2=0.f,a3=0.f;
            for (int ck = 0; ck < 8; ck++){
                __syncthreads();
                {
                    int b = tid >> 2, q = tid & 3;
                    const float* hp = g_h + b*HH + ck*64 + q*16;
                    float* d = hs + b*68 + q*16;
                    #pragma unroll
                    for (int i2=0;i2<4;i2++){
                        float4 v = __ldcv((const float4*)(hp + i2*4));
                        d[i2*4+0]=v.x; d[i2*4+1]=v.y; d[i2*4+2]=v.z; d[i2*4+3]=v.w;
                    }
                }
                __syncthreads();
                const float* wr = Wsl + nl*516 + ck*64;
                const float* h0 = hs + (bg*4+0)*68;
                const float* h1 = hs + (bg*4+1)*68;
                const float* h2 = hs + (bg*4+2)*68;
                const float* h3 = hs + (bg*4+3)*68;
                #pragma unroll
                for (int k4 = 0; k4 < 16; k4++){
                    float4 w  = *(const float4*)(wr + k4*4);
                    float4 ha = *(const float4*)(h0 + k4*4);
                    float4 hb = *(const float4*)(h1 + k4*4);
                    float4 hc = *(const float4*)(h2 + k4*4);
                    float4 hd = *(const float4*)(h3 + k4*4);
                    a0 += w.x*ha.x + w.y*ha.y + w.z*ha.z + w.w*ha.w;
                    a1 += w.x*hb.x + w.y*hb.y + w.z*hb.z + w.w*hb.w;
                    a2 += w.x*hc.x + w.y*hc.y + w.z*hc.z + w.w*hc.w;
                    a3 += w.x*hd.x + w.y*hd.y + w.z*hd.z + w.w*hd.w;
                }
            }
            int n = n0 + nl;
            g_gh[(bg*4+0)*GG + n] = a0;
            g_gh[(bg*4+1)*GG + n] = a1;
            g_gh[(bg*4+2)*GG + n] = a2;
            g_gh[(bg*4+3)*GG + n] = a3;
        }
        gridbar();
        for (int s = bid*256 + tid; s < BB*HH; s += ENB*256){
            int b = s >> 9, j = s & 511;
            float hr, hz, hn2, hprev;
            if (t > 0){
                hr    = __ldcv(&g_gh[b*GG + j]);
                hz    = __ldcv(&g_gh[b*GG + 512 + j]);
                hn2   = __ldcv(&g_gh[b*GG + 1024 + j]);
                hprev = __ldcv(&g_h[b*HH + j]);
            } else { hr=hz=hn2=0.f; hprev=0.f; }
            const float* gi = g_gi + (size_t)(b*SS + t)*GG;
            float r  = sigmoidf_(gi[j]      + hr + bhh[j]);
            float z  = sigmoidf_(gi[512+j]  + hz + bhh[512+j]);
            float nn = tanhf(gi[1024+j] + r*(hn2 + bhh[1024+j]));
            float hnew = (1.0f - z)*nn + z*hprev;
            g_h[b*HH + j] = hnew;
            g_enc[(size_t)(b*SS + t)*HH + j] = hnew;
        }
        gridbar();
    }
}

// decoder K-split GEMM: which==1: A=g_v (K 0..768 -> g_pa); which==2: A=g_v+768 (K 512 -> g_pb)
__global__ __launch_bounds__(256) void k_sgemm_ks(int which,
    const float* __restrict__ W, int ldw, int kchunk)
{
    const float* A; float* Cp;
    if (which == 1) { A = g_v;       Cp = g_pa; }
    else            { A = g_v + 768; Cp = g_pb; }
    __shared__ float As[16][64];
    __shared__ float Ws[16][32];
    int tid = threadIdx.x;
    int n0 = blockIdx.x * 32, kb = blockIdx.y;
    int tx = tid & 15, ty = tid >> 4;
    int ar = tid >> 2, ak = (tid & 3) << 2;
    float acc[4][2] = {};
    const float* Ap = A + (size_t)ar*1280 + ak;
    int k_lo = kb * kchunk, k_hi = k_lo + kchunk;
    for (int k0 = k_lo; k0 < k_hi; k0 += 16) {
        float4 a4 = *(const float4*)(Ap + k0);
        As[ak+0][ar]=a4.x; As[ak+1][ar]=a4.y; As[ak+2][ar]=a4.z; As[ak+3][ar]=a4.w;
        if (tid < 128) {
            int wr = tid >> 2, wk = (tid & 3) << 2;
            float4 w4 = *(const float4*)(W + (size_t)(n0 + wr)*ldw + k0 + wk);
            Ws[wk+0][wr]=w4.x; Ws[wk+1][wr]=w4.y; Ws[wk+2][wr]=w4.z; Ws[wk+3][wr]=w4.w;
        }
        __syncthreads();
        #pragma unroll
        for (int k=0;k<16;k++){
            float4 a = *(const float4*)&As[k][ty<<2];
            float2 b = *(const float2*)&Ws[k][tx<<1];
            acc[0][0]+=a.x*b.x; acc[0][1]+=a.x*b.y;
            acc[1][0]+=a.y*b.x; acc[1][1]+=a.y*b.y;
            acc[2][0]+=a.z*b.x; acc[2][1]+=a.z*b.y;
            acc[3][0]+=a.w*b.x; acc[3][1]+=a.w*b.y;
        }
        __syncthreads();
    }
    float* Co = Cp + (size_t)kb*BB*GG;
    #pragma unroll
    for (int i=0;i<4;i++){
        int m = (ty<<2)+i, n = n0 + (tx<<1);
        Co[(size_t)m*GG + n]   = acc[i][0];
        Co[(size_t)m*GG + n+1] = acc[i][1];
    }
}

__global__ __launch_bounds__(256) void k_dec_gates(const float* __restrict__ bih,
                                                   const float* __restrict__ bhh){
    int idx = blockIdx.x*256 + threadIdx.x;
    int b = idx >> 9, j = idx & 511;
    float ir=0.f, iz=0.f, in_=0.f, hr=0.f, hz=0.f, hn=0.f;
    #pragma unroll
    for (int kb=0;kb<4;kb++){
        const float* pa = g_pa + ((size_t)kb*BB + b)*GG;
        const float* pb = g_pb + ((size_t)kb*BB + b)*GG;
        ir += pa[j]; iz += pa[HH+j]; in_ += pa[2*HH+j];
        hr += pb[j]; hz += pb[HH+j]; hn  += pb[2*HH+j];
    }
    float r = sigmoidf_(ir + bih[j]    + hr + bhh[j]);
    float z = sigmoidf_(iz + bih[HH+j] + hz + bhh[HH+j]);
    float n = tanhf(in_ + bih[2*HH+j] + r*(hn + bhh[2*HH+j]));
    float h = g_v[b*1280 + 768 + j];
    float hnew = (1.0f - z)*n + z*h;
    g_v[b*1280 + 768 + j] = hnew;
    g_u[b*1024 + j]       = hnew;
    g_h[b*HH + j]         = hnew;
}

__global__ __launch_bounds__(512) void k_init_dec(const int* __restrict__ sd,
                                                  const float* __restrict__ emb){
    int b = blockIdx.x, j = threadIdx.x;
    float h = g_h[b*HH + j];
    g_v[b*1280 + 256 + j] = h;
    g_v[b*1280 + 768 + j] = h;
    g_u[b*1024 + 512 + j] = h;
    if (j < EE) g_v[b*1280 + j] = emb[(size_t)sd[b]*EE + j];
}

// fc with packed fma.rn.f32x2: 64x256 tile, 8x8 outputs/thread
__global__ __launch_bounds__(256) void k_fc(const float* __restrict__ Wf,
    const float* __restrict__ bias, float* __restrict__ out, int t)
{
    __shared__ float As[16][64];
    __shared__ float Ws[16][256];
    int tid = threadIdx.x;
    int n0 = blockIdx.x << 8;
    int ty = tid >> 5, tx = tid & 31;
    bool wok = (n0 + tid) < VV;
    const float* wp = Wf + (size_t)(n0 + tid)*1024;
    unsigned long long acc[8][4];
    #pragma unroll
    for (int i=0;i<8;i++){ acc[i][0]=0ull; acc[i][1]=0ull; acc[i][2]=0ull; acc[i][3]=0ull; }

    for (int k0 = 0; k0 < 1024; k0 += 16){
        if (tid < 64){
            const float* ap = g_u + tid*1024 + k0;
            #pragma unroll
            for (int q=0;q<4;q++){
                float4 a = *(const float4*)(ap + q*4);
                As[q*4+0][tid]=a.x; As[q*4+1][tid]=a.y; As[q*4+2][tid]=a.z; As[q*4+3][tid]=a.w;
            }
        }
        #pragma unroll
        for (int q=0;q<4;q++){
            float4 w = wok ? *(const float4*)(wp + k0 + q*4) : make_float4(0.f,0.f,0.f,0.f);
            Ws[q*4+0][tid]=w.x; Ws[q*4+1][tid]=w.y; Ws[q*4+2][tid]=w.z; Ws[q*4+3][tid]=w.w;
        }
        __syncthreads();
        #pragma unroll
        for (int k=0;k<16;k++){
            float4 a0 = *(const float4*)&As[k][ty*8];
            float4 a1 = *(const float4*)&As[k][ty*8+4];
            union { float4 f; unsigned long long u[2]; } w0, w1;
            w0.f = *(const float4*)&Ws[k][tx*4];
            w1.f = *(const float4*)&Ws[k][128 + tx*4];
            float av[8] = {a0.x,a0.y,a0.z,a0.w,a1.x,a1.y,a1.z,a1.w};
            #pragma unroll
            for (int i=0;i<8;i++){
                unsigned long long ad;
                asm("mov.b64 %0,{%1,%1};" : "=l"(ad) : "f"(av[i]));
                asm("fma.rn.f32x2 %0,%1,%2,%0;" : "+l"(acc[i][0]) : "l"(ad), "l"(w0.u[0]));
                asm("fma.rn.f32x2 %0,%1,%2,%0;" : "+l"(acc[i][1]) : "l"(ad), "l"(w0.u[1]));
                asm("fma.rn.f32x2 %0,%1,%2,%0;" : "+l"(acc[i][2]) : "l"(ad), "l"(w1.u[0]));
                asm("fma.rn.f32x2 %0,%1,%2,%0;" : "+l"(acc[i][3]) : "l"(ad), "l"(w1.u[1]));
            }
        }
        __syncthreads();
    }

    int nA = n0 + tx*4, nB = n0 + 128 + tx*4;
    float bb[8];
    #pragma unroll
    for (int j=0;j<4;j++){
        bb[j]   = (nA+j < VV) ? bias[nA+j] : 0.f;
        bb[4+j] = (nB+j < VV) ? bias[nB+j] : 0.f;
    }
    #pragma unroll
    for (int i=0;i<8;i++){
        int m = ty*8 + i;
        size_t orow = ((size_t)(m*TT + t))*VV;
        union { unsigned long long u; float2 f; } q0,q1,q2,q3;
        q0.u=acc[i][0]; q1.u=acc[i][1]; q2.u=acc[i][2]; q3.u=acc[i][3];
        float vals[8]={q0.f.x,q0.f.y,q1.f.x,q1.f.y,q2.f.x,q2.f.y,q3.f.x,q3.f.y};
        float bv = -3.4e38f; int bi = 0x7fffffff;
        #pragma unroll
        for (int j=0;j<8;j++){
            int n = (j<4) ? (nA+j) : (nB+j-4);
            if (n < VV){
                float val = vals[j] + bb[j];
                out[orow + n] = val;
                if (val > bv) { bv = val; bi = n; }   // ascending n: > keeps lowest
            }
        }
        #pragma unroll
        for (int o=16;o>0;o>>=1){
            float v2 = __shfl_xor_sync(0xffffffffu, bv, o);
            int   i2 = __shfl_xor_sync(0xffffffffu, bi, o);
            if (v2 > bv || (v2 == bv && i2 < bi)){ bv = v2; bi = i2; }
        }
        if (tx == 0){
            g_pmax[m*128 + blockIdx.x] = bv;
            g_pidx[m*128 + blockIdx.x] = bi;
        }
    }
}

__global__ __launch_bounds__(256) void k_argmax(const float* __restrict__ emb){
    int b = blockIdx.x, tid = threadIdx.x;
    __shared__ float sv[256];
    __shared__ int   si[256];
    float v = -3.4e38f; int idx = 0x7fffffff;
    if (tid < NBF){ v = g_pmax[b*128+tid]; idx = g_pidx[b*128+tid]; }
    sv[tid]=v; si[tid]=idx;
    __syncthreads();
    for (int o=128;o>0;o>>=1){
        if (tid < o){
            float v2=sv[tid+o]; int i2=si[tid+o];
            if (v2>sv[tid] || (v2==sv[tid] && i2<si[tid])){ sv[tid]=v2; si[tid]=i2; }
        }
        __syncthreads();
    }
    g_v[b*1280 + tid] = emb[(size_t)si[0]*EE + tid];
}

__global__ __launch_bounds__(512) void k_attn(){
    int b = blockIdx.x, tid = threadIdx.x;
    int w = tid >> 5, lane = tid & 31;
    __shared__ float sc[SS];
    const float* hb = g_h + b*HH;
    #pragma unroll
    for (int r = 0; r < 4; r++){
        int s = w*4 + r;
        const float* tp = g_temp + ((size_t)(b*SS+s))*HH;
        float acc = 0.f;
        for (int j = lane; j < HH; j += 32) acc += tp[j]*hb[j];
        #pragma unroll
        for (int o=16;o>0;o>>=1) acc += __shfl_xor_sync(0xffffffffu, acc, o);
        if (lane==0) sc[s] = acc;
    }
    __syncthreads();
    if (w == 0){
        float v0 = sc[lane], v1 = sc[lane+32];
        float m = fmaxf(v0,v1);
        #pragma unroll
        for(int o=16;o>0;o>>=1) m = fmaxf(m, __shfl_xor_sync(0xffffffffu,m,o));
        float e0 = expf(v0-m), e1 = expf(v1-m);
        float s = e0+e1;
        #pragma unroll
        for(int o=16;o>0;o>>=1) s += __shfl_xor_sync(0xffffffffu,s,o);
        sc[lane] = e0/s; sc[lane+32] = e1/s;
    }
    __syncthreads();
    const float* eb = g_enc + (size_t)b*SS*HH + tid;
    float ctx = 0.f;
    #pragma unroll 8
    for (int s=0;s<SS;s++) ctx += sc[s]*eb[(size_t)s*HH];
    g_v[b*1280 + 256 + tid] = ctx;
    g_u[b*1024 + 512 + tid] = ctx;
}

extern "C" void kernel_launch(void* const* d_in, const int* in_sizes, int n_in,
                              void* d_out, int out_size){
    int off = (n_in >= 16) ? 1 : 0;
    const int*   x    = (const int*)d_in[0];
    const int*   sd   = (const int*)d_in[1];
    const float* emb  = (const float*)d_in[2+off];
    const float* eWih = (const float*)d_in[3+off];
    const float* eWhh = (const float*)d_in[4+off];
    const float* ebih = (const float*)d_in[5+off];
    const float* ebhh = (const float*)d_in[6+off];
    const float* dWih = (const float*)d_in[7+off];
    const float* dWhh = (const float*)d_in[8+off];
    const float* dbih = (const float*)d_in[9+off];
    const float* dbhh = (const float*)d_in[10+off];
    const float* fcW  = (const float*)d_in[11+off];
    const float* fcb  = (const float*)d_in[12+off];
    const float* aW   = (const float*)d_in[13+off];
    const float* ab   = (const float*)d_in[14+off];
    float* out = (float*)d_out;

    static int smem_set = 0;
    if (!smem_set){
        cudaFuncSetAttribute(k_encoder, cudaFuncAttributeMaxDynamicSharedMemorySize, SMEM_ENC);
        smem_set = 1;
    }

    k_embed<<<BB*SS,64>>>(x, emb);
    k_sgemm<<<dim3(GG/64, BB*SS/64),256>>>(0, eWih, EE, ebih, EE);
    k_encoder<<<ENB,256,SMEM_ENC>>>(eWhh, ebhh);
    k_sgemm<<<dim3(HH/64, BB*SS/64),256>>>(1, aW, HH, ab, HH);
    k_init_dec<<<BB,512>>>(sd, emb);
    for (int t=0;t<TT;t++){
        k_sgemm_ks<<<dim3(48,4),256>>>(1, dWih, 768, 192);
        k_sgemm_ks<<<dim3(48,4),256>>>(2, dWhh, HH, 128);
        k_dec_gates<<<128,256>>>(dbih, dbhh);
        k_fc<<<NBF,256>>>(fcW, fcb, out, t);
        k_argmax<<<BB,256>>>(emb);
        k_attn<<<BB,512>>>();
    }
}